// round 4
// baseline (speedup 1.0000x reference)
#include <cuda_runtime.h>
#include <cstdint>

#define N_IDX 4096

// Per-index bilinear metadata for levels f1/f2/f3 (f0 is identity gather).
struct __align__(16) Meta {
    int   p00;  // y0c*W + x0c
    int   d;    // (dyRow << 16) | dxCol
    float wy;
    float wx;
};

__device__ Meta g_meta[3 * N_IDX];

__global__ void precompute_meta(const int* __restrict__ indices) {
    int t = blockIdx.x * blockDim.x + threadIdx.x;
    if (t >= 3 * N_IDX) return;
    int lvl = t / N_IDX;        // 0 -> f1 (H=128), 1 -> f2 (64), 2 -> f3 (32)
    int j   = t - lvl * N_IDX;
    int H   = 128 >> lvl;
    float scale = (float)H * (1.0f / 256.0f);

    int idx = indices[j];
    int iy = idx >> 8;
    int ix = idx & 255;
    // half-pixel centers (align_corners=False)
    float sy = ((float)iy + 0.5f) * scale - 0.5f;
    float sx = ((float)ix + 0.5f) * scale - 0.5f;
    float y0f = floorf(sy), x0f = floorf(sx);
    float wy = sy - y0f,    wx = sx - x0f;
    int y0 = (int)y0f, x0 = (int)x0f;
    int y0c = min(max(y0,     0), H - 1);
    int y1c = min(max(y0 + 1, 0), H - 1);
    int x0c = min(max(x0,     0), H - 1);
    int x1c = min(max(x0 + 1, 0), H - 1);

    Meta m;
    m.p00 = y0c * H + x0c;
    m.d   = (((y1c - y0c) * H) << 16) | (x1c - x0c);
    m.wy  = wy;
    m.wx  = wx;
    g_meta[t] = m;
}

// One fused kernel; CTA role by blockIdx range:
//   [0,1024)    : f1 — 512 planes x 2 row-halves, half-plane staged in smem
//   [1024,1536) : f2 — 2 channels interleaved per CTA (LDS.64 taps)
//   [1536,1792) : f3 — 8 channels interleaved per CTA (LDS.128 taps)
//   [1792,2304) : f0 — identity LDG gather (2 CTAs per plane)
__global__ __launch_bounds__(256) void fused_gather(
    const float* __restrict__ f0, const float* __restrict__ f1,
    const float* __restrict__ f2, const float* __restrict__ f3,
    const int*   __restrict__ indices, float* __restrict__ out)
{
    extern __shared__ float s[];
    int bid = blockIdx.x;
    int tid = threadIdx.x;

    if (bid < 1024) {
        // ---- f1: H=128, plane 64KB -> two 33.3KB half-plane CTAs ----
        int plane = bid >> 1, half = bid & 1;
        int b = plane >> 7, c = plane & 127;
        int r0 = half << 6;                       // 0 or 64
        int nrows = 65 - half;                    // rows [0,65) or [64,128)
        const float4* src4 =
            (const float4*)(f1 + (size_t)(b * 128 + c) * 16384 + r0 * 128);
        float4* s4 = (float4*)s;
        for (int i = tid; i < nrows * 32; i += 256) s4[i] = src4[i];
        __syncthreads();

        const int4* meta = (const int4*)(g_meta);
        float* o = out + (size_t)(b * 960 + 64 + c) * N_IDX;
        int base = r0 << 7;
        for (int j = tid; j < N_IDX; j += 256) {
            int4 mr = __ldg(meta + j);
            int p00 = mr.x;
            // my row-half? (y1c = y0c+1 never crosses the staged boundary)
            if (((p00 >> 13) & 1) == half) {
                int sp = p00 - base;
                int dy = mr.y >> 16, dx = mr.y & 0xffff;
                float wy = __int_as_float(mr.z), wx = __int_as_float(mr.w);
                float v00 = s[sp];
                float v01 = s[sp + dx];
                float v10 = s[sp + dy];
                float v11 = s[sp + dy + dx];
                float top = v00 + wx * (v01 - v00);
                float bot = v10 + wx * (v11 - v10);
                o[j] = top + wy * (bot - top);
            }
        }
    } else if (bid < 1536) {
        // ---- f2: H=64, 2 channels interleaved: s[2p+cc] ----
        int rel = bid - 1024;
        int b = rel >> 7, cg = rel & 127;
        int c0 = cg * 2;
        const float2* p0 = (const float2*)(f2 + (size_t)(b * 256 + c0) * 4096);
        const float2* p1 = (const float2*)(f2 + (size_t)(b * 256 + c0 + 1) * 4096);
        float4* s4 = (float4*)s;
        for (int i = tid; i < 2048; i += 256) {
            float2 a = __ldg(p0 + i), bb = __ldg(p1 + i);
            s4[i] = make_float4(a.x, bb.x, a.y, bb.y);
        }
        __syncthreads();

        const int4* meta = (const int4*)(g_meta + N_IDX);
        float* o = out + (size_t)(b * 960 + 192 + c0) * N_IDX;
        for (int j = tid; j < N_IDX; j += 256) {
            int4 mr = __ldg(meta + j);
            int p00 = mr.x;
            int dy = mr.y >> 16, dx = mr.y & 0xffff;
            float wy = __int_as_float(mr.z), wx = __int_as_float(mr.w);
            float2 v00 = *(const float2*)(s + 2 * p00);
            float2 v01 = *(const float2*)(s + 2 * (p00 + dx));
            float2 v10 = *(const float2*)(s + 2 * (p00 + dy));
            float2 v11 = *(const float2*)(s + 2 * (p00 + dy + dx));
            float t0 = v00.x + wx * (v01.x - v00.x);
            float b0 = v10.x + wx * (v11.x - v10.x);
            o[j] = t0 + wy * (b0 - t0);
            float t1 = v00.y + wx * (v01.y - v00.y);
            float b1 = v10.y + wx * (v11.y - v10.y);
            o[N_IDX + j] = t1 + wy * (b1 - t1);
        }
    } else if (bid < 1792) {
        // ---- f3: H=32, 8 channels interleaved: s[8p+cc], 32KB ----
        int rel = bid - 1536;
        int b = rel >> 6, cg = rel & 63;
        int c0 = cg * 8;
        const float* src = f3 + (size_t)(b * 512 + c0) * 1024;
        float4* s4 = (float4*)s;
        for (int p = tid; p < 1024; p += 256) {
            float4 a, q;
            a.x = __ldg(src +    0 + p); a.y = __ldg(src + 1024 + p);
            a.z = __ldg(src + 2048 + p); a.w = __ldg(src + 3072 + p);
            q.x = __ldg(src + 4096 + p); q.y = __ldg(src + 5120 + p);
            q.z = __ldg(src + 6144 + p); q.w = __ldg(src + 7168 + p);
            s4[p * 2]     = a;
            s4[p * 2 + 1] = q;
        }
        __syncthreads();

        const int4* meta = (const int4*)(g_meta + 2 * N_IDX);
        float* o = out + (size_t)(b * 960 + 448 + c0) * N_IDX;
        for (int j = tid; j < N_IDX; j += 256) {
            int4 mr = __ldg(meta + j);
            int p00 = mr.x;
            int dy = mr.y >> 16, dx = mr.y & 0xffff;
            float wy = __int_as_float(mr.z), wx = __int_as_float(mr.w);
            int i00 = 2 * p00, i01 = 2 * (p00 + dx);
            int i10 = 2 * (p00 + dy), i11 = 2 * (p00 + dy + dx);
            float4 a00 = s4[i00], b00 = s4[i00 + 1];
            float4 a01 = s4[i01], b01 = s4[i01 + 1];
            float4 a10 = s4[i10], b10 = s4[i10 + 1];
            float4 a11 = s4[i11], b11 = s4[i11 + 1];
            #define LERP2(v00v, v01v, v10v, v11v, cc)                         \
                { float tp = v00v + wx * (v01v - v00v);                       \
                  float bt = v10v + wx * (v11v - v10v);                       \
                  o[(cc) * N_IDX + j] = tp + wy * (bt - tp); }
            LERP2(a00.x, a01.x, a10.x, a11.x, 0)
            LERP2(a00.y, a01.y, a10.y, a11.y, 1)
            LERP2(a00.z, a01.z, a10.z, a11.z, 2)
            LERP2(a00.w, a01.w, a10.w, a11.w, 3)
            LERP2(b00.x, b01.x, b10.x, b11.x, 4)
            LERP2(b00.y, b01.y, b10.y, b11.y, 5)
            LERP2(b00.z, b01.z, b10.z, b11.z, 6)
            LERP2(b00.w, b01.w, b10.w, b11.w, 7)
            #undef LERP2
        }
    } else {
        // ---- f0: identity gather, 2 CTAs per plane for more MLP spread ----
        int rel = bid - 1792;
        int plane = rel >> 1, half = rel & 1;
        int b = plane >> 6, c = plane & 63;
        const float* plane_p = f0 + (size_t)(b * 64 + c) * 65536;
        float* o = out + (size_t)(b * 960 + c) * N_IDX;
        int j0 = half * 2048;
        #pragma unroll 4
        for (int j = j0 + tid; j < j0 + 2048; j += 256)
            o[j] = __ldg(plane_p + __ldg(indices + j));
    }
}

extern "C" void kernel_launch(void* const* d_in, const int* in_sizes, int n_in,
                              void* d_out, int out_size) {
    const float* f0 = nullptr; const float* f1 = nullptr;
    const float* f2 = nullptr; const float* f3 = nullptr;
    const int* indices = nullptr;
    for (int i = 0; i < n_in; i++) {
        switch (in_sizes[i]) {
            case 16777216: f0 = (const float*)d_in[i]; break;
            case 8388608:  f1 = (const float*)d_in[i]; break;
            case 4194304:  f2 = (const float*)d_in[i]; break;
            case 2097152:  f3 = (const float*)d_in[i]; break;
            case N_IDX:    indices = (const int*)d_in[i]; break;
        }
    }
    if (!f0 || !f1 || !f2 || !f3 || !indices) {
        f0 = (const float*)d_in[0];
        f1 = (const float*)d_in[1];
        f2 = (const float*)d_in[2];
        f3 = (const float*)d_in[3];
        indices = (const int*)d_in[4];
    }
    float* out = (float*)d_out;

    precompute_meta<<<(3 * N_IDX + 255) / 256, 256>>>(indices);

    // 65 rows * 128 cols * 4B = 33280 B dynamic smem (uniform, <48KB default).
    fused_gather<<<2304, 256, 33280>>>(f0, f1, f2, f3, indices, out);
}